// round 8
// baseline (speedup 1.0000x reference)
#include <cuda_runtime.h>
#include <cstdint>

// MultiNetwork: 32 MLPs 256->512->512->128 (relu, relu, id), batch 4096.
// Round 8: mma.sync tf32. CTA 128x256, 512 threads (16 warps of 64x32),
// cp.async for BOTH operands (all pre-rounded in global scratch), ldmatrix
// fragments, 3-stage single-sync pipeline. 2 launches total (round + main).

#define DINLINE __device__ __forceinline__

static constexpr int NETS  = 32;
static constexpr int BATCH = 4096;
static constexpr int D_IN  = 256;
static constexpr int D_H   = 512;
static constexpr int D_OUT = 128;

static constexpr int MT = 128;    // CTA batch tile
static constexpr int KC = 32;     // K chunk
static constexpr int LD = 36;     // padded smem row stride (floats)

static constexpr int A_F = MT * LD;              // 4608 floats
static constexpr int B_F = 256 * LD;             // 9216 floats (max Nc)
static constexpr int A_BYTES     = A_F * 4;
static constexpr int STAGE_F     = A_F + B_F;    // 13824
static constexpr int STAGE_BYTES = STAGE_F * 4;  // 55296
static constexpr int SMEM_BYTES  = 3 * STAGE_BYTES;  // 165888

// Pre-rounded (tf32/rna) operands + inter-layer activations.
__device__ float g_xr [(size_t)BATCH * D_IN];
__device__ float g_w1r[(size_t)NETS * D_H   * D_IN];
__device__ float g_w2r[(size_t)NETS * D_H   * D_H];
__device__ float g_w3r[(size_t)NETS * D_OUT * D_H];
__device__ float g_h1 [(size_t)NETS * BATCH * D_H];
__device__ float g_h2 [(size_t)NETS * BATCH * D_H];

DINLINE uint32_t smem_u32(const void* p) {
    uint32_t a;
    asm("{ .reg .u64 t; cvta.to.shared.u64 t, %1; cvt.u32.u64 %0, t; }" : "=r"(a) : "l"(p));
    return a;
}
DINLINE uint32_t tf32r(float x) {
    uint32_t u;
    asm("cvt.rna.tf32.f32 %0, %1;" : "=r"(u) : "f"(x));
    return u;
}
DINLINE void cpasync16(uint32_t dst, const void* src) {
    asm volatile("cp.async.cg.shared.global [%0], [%1], 16;"
                 :: "r"(dst), "l"(src) : "memory");
}
DINLINE void cp_commit() { asm volatile("cp.async.commit_group;" ::: "memory"); }
DINLINE void cp_wait1()  { asm volatile("cp.async.wait_group 1;" ::: "memory"); }

DINLINE void ldsm4(uint32_t* r, uint32_t addr) {
    asm volatile("ldmatrix.sync.aligned.m8n8.x4.shared.b16 {%0,%1,%2,%3}, [%4];"
                 : "=r"(r[0]), "=r"(r[1]), "=r"(r[2]), "=r"(r[3]) : "r"(addr));
}
DINLINE void mma8(float* d, const uint32_t* a, const uint32_t* b) {
    asm volatile(
        "mma.sync.aligned.m16n8k8.row.col.f32.tf32.tf32.f32 "
        "{%0,%1,%2,%3}, {%4,%5,%6,%7}, {%8,%9}, {%0,%1,%2,%3};"
        : "+f"(d[0]), "+f"(d[1]), "+f"(d[2]), "+f"(d[3])
        : "r"(a[0]), "r"(a[1]), "r"(a[2]), "r"(a[3]), "r"(b[0]), "r"(b[1]));
}

// GEMM segment: C[128, WGN*NF*8] = A[128,K] * B^T (+bias, optional relu).
// Warp grid WGM x WGN (WGM*WGN == 16), warp tile (MF*16) x (NF*8).
template<int WGM, int WGN, int MF, int NF, bool ISOUT>
DINLINE void run_segment(const float* __restrict__ Asrc, int As, int K,
                         const float* __restrict__ Bsrc,
                         const float* __restrict__ bias,
                         float* __restrict__ dst, int dstride)
{
    extern __shared__ float smf[];
    const uint32_t sb = smem_u32(smf);
    const int tid  = threadIdx.x;
    const int lane = tid & 31, wid = tid >> 5;
    const int gid  = lane >> 2, tig = lane & 3;
    const int wm   = wid % WGM, wn = wid / WGM;

    constexpr int NC = WGN * NF * 8;
    const int nk = K / KC;

    float acc[MF][NF][4];
    #pragma unroll
    for (int i = 0; i < MF; i++)
        #pragma unroll
        for (int j = 0; j < NF; j++)
            #pragma unroll
            for (int q = 0; q < 4; q++) acc[i][j][q] = 0.0f;

    auto issue = [&](int kk, int st) {
        const uint32_t base = sb + st * STAGE_BYTES;
        #pragma unroll
        for (int i = 0; i < (MT * 8) / 512; i++) {        // A: 2 quads/thread
            int f = tid + i * 512, r = f >> 3, c = f & 7;
            cpasync16(base + (uint32_t)(r * LD + c * 4) * 4,
                      Asrc + (size_t)r * As + kk * KC + c * 4);
        }
        #pragma unroll
        for (int i = 0; i < (NC * 8) / 512; i++) {        // B: NC/64 quads/thread
            int f = tid + i * 512, r = f >> 3, c = f & 7;
            cpasync16(base + A_BYTES + (uint32_t)(r * LD + c * 4) * 4,
                      Bsrc + (size_t)r * K + kk * KC + c * 4);
        }
    };

    // per-lane ldmatrix byte offsets
    const uint32_t aoff = (uint32_t)(((lane & 15) * LD + ((lane >> 4) & 1) * 4) * 4);
    const uint32_t boff = (uint32_t)(((((lane >> 4) & 1) * 8 + (lane & 7)) * LD
                                      + ((lane >> 3) & 1) * 4) * 4);

    auto compute = [&](int st) {
        const uint32_t Ab = sb + st * STAGE_BYTES
                          + (uint32_t)(wm * MF * 16 * LD * 4) + aoff;
        const uint32_t Bb = sb + st * STAGE_BYTES + A_BYTES
                          + (uint32_t)(wn * NF * 8 * LD * 4) + boff;
        #pragma unroll
        for (int ks = 0; ks < 4; ks++) {
            const uint32_t k0b = (uint32_t)(ks * 32);
            uint32_t a[MF][4];
            #pragma unroll
            for (int mf = 0; mf < MF; mf++)
                ldsm4(a[mf], Ab + (uint32_t)(mf * 16 * LD * 4) + k0b);
            #pragma unroll
            for (int p = 0; p < NF / 2; p++) {
                uint32_t bt[4];
                ldsm4(bt, Bb + (uint32_t)(p * 16 * LD * 4) + k0b);
                #pragma unroll
                for (int mf = 0; mf < MF; mf++) {
                    mma8(acc[mf][2 * p],     a[mf], bt);
                    mma8(acc[mf][2 * p + 1], a[mf], bt + 2);
                }
            }
        }
    };

    // ---- 3-stage pipeline, one __syncthreads per chunk ----
    issue(0, 0); cp_commit();
    issue(1, 1); cp_commit();

    int st = 0, st2 = 2;
    for (int kk = 0; kk < nk; kk++) {
        cp_wait1();
        __syncthreads();
        if (kk + 2 < nk) issue(kk + 2, st2);
        cp_commit();
        compute(st);
        st  = (st  == 2) ? 0 : st  + 1;
        st2 = (st2 == 2) ? 0 : st2 + 1;
    }

    // ---- epilogue ----
    #pragma unroll
    for (int mf = 0; mf < MF; mf++) {
        #pragma unroll
        for (int nf = 0; nf < NF; nf++) {
            const int rr  = wm * MF * 16 + mf * 16 + gid;
            const int col = wn * NF * 8 + nf * 8 + tig * 2;
            const float b0 = __ldg(bias + col), b1 = __ldg(bias + col + 1);
            float v00 = acc[mf][nf][0] + b0, v01 = acc[mf][nf][1] + b1;
            float v10 = acc[mf][nf][2] + b0, v11 = acc[mf][nf][3] + b1;
            if (!ISOUT) {
                v00 = fmaxf(v00, 0.0f); v01 = fmaxf(v01, 0.0f);
                v10 = fmaxf(v10, 0.0f); v11 = fmaxf(v11, 0.0f);
                float2 lo = make_float2(__uint_as_float(tf32r(v00)),
                                        __uint_as_float(tf32r(v01)));
                float2 hi = make_float2(__uint_as_float(tf32r(v10)),
                                        __uint_as_float(tf32r(v11)));
                *reinterpret_cast<float2*>(dst + (size_t)rr * dstride + col) = lo;
                *reinterpret_cast<float2*>(dst + (size_t)(rr + 8) * dstride + col) = hi;
            } else {
                *reinterpret_cast<float2*>(dst + (size_t)rr * dstride + col) =
                    make_float2(v00, v01);
                *reinterpret_cast<float2*>(dst + (size_t)(rr + 8) * dstride + col) =
                    make_float2(v10, v11);
            }
        }
    }
    if (!ISOUT) asm volatile("membar.gl;" ::: "memory");  // h -> next cp.async
    __syncthreads();
}

__global__ void __launch_bounds__(512, 1)
multinet8(const float* __restrict__ b1, const float* __restrict__ b2,
          const float* __restrict__ b3, float* __restrict__ out)
{
    const int m0 = blockIdx.x * MT;
    const int g  = blockIdx.y;

    float* h1 = g_h1 + ((size_t)g * BATCH + m0) * D_H;
    float* h2 = g_h2 + ((size_t)g * BATCH + m0) * D_H;
    const float* xa = g_xr + (size_t)m0 * D_IN;

    // layer 1: two 256-wide segments (warp grid 2x8, warp tile 64x32)
    run_segment<2, 8, 4, 4, false>(xa, D_IN, D_IN,
                                   g_w1r + (size_t)g * D_H * D_IN,
                                   b1 + (size_t)g * D_H, h1, D_H);
    run_segment<2, 8, 4, 4, false>(xa, D_IN, D_IN,
                                   g_w1r + ((size_t)g * D_H + 256) * D_IN,
                                   b1 + (size_t)g * D_H + 256, h1 + 256, D_H);
    // layer 2
    run_segment<2, 8, 4, 4, false>(h1, D_H, D_H,
                                   g_w2r + (size_t)g * D_H * D_H,
                                   b2 + (size_t)g * D_H, h2, D_H);
    run_segment<2, 8, 4, 4, false>(h1, D_H, D_H,
                                   g_w2r + ((size_t)g * D_H + 256) * D_H,
                                   b2 + (size_t)g * D_H + 256, h2 + 256, D_H);
    // layer 3 (identity, N=128; warp grid 4x4, warp tile 32x32)
    run_segment<4, 4, 2, 4, true>(h2, D_H, D_H,
                                  g_w3r + (size_t)g * D_OUT * D_H,
                                  b3 + (size_t)g * D_OUT,
                                  out + (size_t)m0 * (NETS * D_OUT) + g * D_OUT,
                                  NETS * D_OUT);
}

// Fused fp32 -> tf32(rna) pre-round of x, W1, W2, W3 (one launch).
__global__ void round_all(const float* __restrict__ x,
                          const float* __restrict__ W1,
                          const float* __restrict__ W2,
                          const float* __restrict__ W3)
{
    constexpr size_t N0 = (size_t)BATCH * D_IN / 4;
    constexpr size_t N1 = (size_t)NETS * D_H * D_IN / 4;
    constexpr size_t N2 = (size_t)NETS * D_H * D_H / 4;
    constexpr size_t N3 = (size_t)NETS * D_OUT * D_H / 4;

    size_t j = (size_t)blockIdx.x * blockDim.x + threadIdx.x;
    const float4* src; float4* dst;
    if (j < N0)              { src = (const float4*)x;  dst = (float4*)g_xr; }
    else if ((j -= N0) < N1) { src = (const float4*)W1; dst = (float4*)g_w1r; }
    else if ((j -= N1) < N2) { src = (const float4*)W2; dst = (float4*)g_w2r; }
    else if ((j -= N2) < N3) { src = (const float4*)W3; dst = (float4*)g_w3r; }
    else return;

    float4 v = src[j];
    dst[j] = make_float4(__uint_as_float(tf32r(v.x)), __uint_as_float(tf32r(v.y)),
                         __uint_as_float(tf32r(v.z)), __uint_as_float(tf32r(v.w)));
}

extern "C" void kernel_launch(void* const* d_in, const int* in_sizes, int n_in,
                              void* d_out, int out_size)
{
    const float* x  = (const float*)d_in[0];
    const float* W1 = (const float*)d_in[1];
    const float* b1 = (const float*)d_in[2];
    const float* W2 = (const float*)d_in[3];
    const float* b2 = (const float*)d_in[4];
    const float* W3 = (const float*)d_in[5];
    const float* b3 = (const float*)d_in[6];
    float* out = (float*)d_out;

    constexpr size_t TOTQ = ((size_t)BATCH * D_IN + (size_t)NETS * D_H * D_IN
                           + (size_t)NETS * D_H * D_H + (size_t)NETS * D_OUT * D_H) / 4;
    round_all<<<(unsigned)((TOTQ + 255) / 256), 256>>>(x, W1, W2, W3);

    cudaFuncSetAttribute(multinet8,
                         cudaFuncAttributeMaxDynamicSharedMemorySize, SMEM_BYTES);
    dim3 grid(BATCH / MT, NETS);   // 32 x 32 = 1024 CTAs
    multinet8<<<grid, 512, SMEM_BYTES>>>(b1, b2, b3, out);
}